// round 1
// baseline (speedup 1.0000x reference)
#include <cuda_runtime.h>

#define DD   128     // feature dim
#define NNB  32      // neighbors
#define LRELU_ALPHA 0.2f

// Fused GAT aggregation, one CTA per batch element.
//   message[n][e] = sum_d nb[n][d] * w[d][e]        (32x128x128 GEMM, registers)
//   score[n]      = sum_e lrelu(self[e]*message)*q[e]
//   alpha         = softmax(score)                   (over 32 neighbors)
//   out[e]        = sum_d (sum_n alpha[n]*nb[n][d]) * w[d][e]   <-- algebraic refactor:
// the weighted sum commutes with the linear map, so message is never stored.
extern "C" __global__ void __launch_bounds__(256, 2)
gat_fused(const float* __restrict__ self_v,
          const float* __restrict__ nbv,
          const float* __restrict__ w,
          const float* __restrict__ q,
          float* __restrict__ out)
{
    extern __shared__ float sm[];
    float* w_s     = sm;                  // 128*128 = 16384 floats (row d, col e)
    float* nb_s    = w_s + DD * DD;       // 32*128  =  4096 floats
    float* self_s  = nb_s + NNB * DD;     // 128
    float* q_s     = self_s + DD;         // 128
    float* score_s = q_s + DD;            // 32
    float* alpha_s = score_s + NNB;       // 32
    float* agg_s   = alpha_s + NNB;       // 128

    const int b = blockIdx.x;
    const int t = threadIdx.x;

    // ---- cooperative loads ----
    const float4* wg   = reinterpret_cast<const float4*>(w);
    float4*       ws4  = reinterpret_cast<float4*>(w_s);
    #pragma unroll
    for (int i = 0; i < (DD * DD / 4) / 256; ++i)       // 16 iters
        ws4[t + i * 256] = wg[t + i * 256];

    const float4* nbg  = reinterpret_cast<const float4*>(nbv + (size_t)b * NNB * DD);
    float4*       nbs4 = reinterpret_cast<float4*>(nb_s);
    #pragma unroll
    for (int i = 0; i < (NNB * DD / 4) / 256; ++i)      // 4 iters
        nbs4[t + i * 256] = nbg[t + i * 256];

    if (t < DD) {
        self_s[t] = self_v[(size_t)b * DD + t];
        q_s[t]    = q[t];                                // q is (D,1) contiguous
    }
    __syncthreads();

    // ---- message GEMM: 32x128 tile, thread tile = 4n x 4e ----
    // warp r (0..7) owns n in {r, r+8, r+16, r+24}; lane c owns e in {4c..4c+3}
    const int r = t >> 5;
    const int c = t & 31;

    float acc[4][4] = {};                                // [n_i][e_j]
    const float* nb0 = nb_s + r * DD;

    #pragma unroll 4
    for (int d = 0; d < DD; ++d) {
        const float4 wv = ws4[d * (DD / 4) + c];         // LDS.128, conflict-free
        const float wf[4] = { wv.x, wv.y, wv.z, wv.w };
        const float a0 = nb0[d];                         // broadcast reads
        const float a1 = nb0[d +  8 * DD];
        const float a2 = nb0[d + 16 * DD];
        const float a3 = nb0[d + 24 * DD];
        const float af[4] = { a0, a1, a2, a3 };
        #pragma unroll
        for (int i = 0; i < 4; ++i)
            #pragma unroll
            for (int j = 0; j < 4; ++j)
                acc[i][j] = fmaf(af[i], wf[j], acc[i][j]);
    }

    // ---- per-(n) score partials: lrelu(self*m)*q, reduced over e ----
    float p[4] = { 0.f, 0.f, 0.f, 0.f };
    #pragma unroll
    for (int j = 0; j < 4; ++j) {
        const int e = 4 * c + j;
        const float se = self_s[e];
        const float qe = q_s[e];
        #pragma unroll
        for (int i = 0; i < 4; ++i) {
            float v = se * acc[i][j];
            v = (v >= 0.f) ? v : LRELU_ALPHA * v;
            p[i] = fmaf(v, qe, p[i]);
        }
    }
    #pragma unroll
    for (int off = 16; off > 0; off >>= 1) {
        #pragma unroll
        for (int i = 0; i < 4; ++i)
            p[i] += __shfl_xor_sync(0xffffffffu, p[i], off);
    }
    if (c == 0) {
        #pragma unroll
        for (int i = 0; i < 4; ++i)
            score_s[r + 8 * i] = p[i];
    }
    __syncthreads();

    // ---- softmax over 32 neighbors (warp 0) ----
    if (t < 32) {
        const float s = score_s[t];
        float mx = s;
        #pragma unroll
        for (int off = 16; off > 0; off >>= 1)
            mx = fmaxf(mx, __shfl_xor_sync(0xffffffffu, mx, off));
        const float ex = __expf(s - mx);
        float sum = ex;
        #pragma unroll
        for (int off = 16; off > 0; off >>= 1)
            sum += __shfl_xor_sync(0xffffffffu, sum, off);
        alpha_s[t] = ex / sum;
    }
    __syncthreads();

    // ---- agg[d] = sum_n alpha[n] * nb[n][d] ----
    if (t < DD) {
        float a = 0.f;
        #pragma unroll
        for (int n = 0; n < NNB; ++n)
            a = fmaf(alpha_s[n], nb_s[n * DD + t], a);
        agg_s[t] = a;
    }
    __syncthreads();

    // ---- out[e] = sum_d agg[d] * w[d][e] ----
    if (t < DD) {
        float o = 0.f;
        #pragma unroll 8
        for (int d = 0; d < DD; ++d)
            o = fmaf(agg_s[d], w_s[d * DD + t], o);
        out[(size_t)b * DD + t] = o;
    }
}

extern "C" void kernel_launch(void* const* d_in, const int* in_sizes, int n_in,
                              void* d_out, int out_size)
{
    const float* self_v = (const float*)d_in[0];   // [B,128]
    const float* nbv    = (const float*)d_in[1];   // [B,32,128]
    const float* w      = (const float*)d_in[2];   // [128,128]
    const float* q      = (const float*)d_in[3];   // [128,1]
    float*       out    = (float*)d_out;           // [B,128]

    const int B = in_sizes[0] / DD;                // 20000

    const size_t smem_bytes =
        (size_t)(DD * DD + NNB * DD + DD + DD + NNB + NNB + DD) * sizeof(float); // 83712

    cudaFuncSetAttribute(gat_fused, cudaFuncAttributeMaxDynamicSharedMemorySize,
                         (int)smem_bytes);

    gat_fused<<<B, 256, smem_bytes>>>(self_v, nbv, w, q, out);
}

// round 2
// speedup vs baseline: 2.2003x; 2.2003x over previous
#include <cuda_runtime.h>
#include <cstdint>

#define DD    128     // feature dim
#define NNB   32      // neighbors
#define BPC   2       // batches per CTA
#define ROWS  (BPC * NNB)        // 64 GEMM rows
#define STR   132     // padded smem row stride (floats) -> conflict-free frags
#define LRELU_ALPHA 0.2f

__device__ __forceinline__ uint32_t f2tf32(float f) {
    uint32_t r;
    asm("cvt.rna.tf32.f32 %0, %1;" : "=r"(r) : "f"(f));
    return r;
}

__device__ __forceinline__ void mma_tf32(float& c0, float& c1, float& c2, float& c3,
                                         uint32_t a0, uint32_t a1, uint32_t a2, uint32_t a3,
                                         uint32_t b0, uint32_t b1) {
    asm volatile(
        "mma.sync.aligned.m16n8k8.row.col.f32.tf32.tf32.f32 "
        "{%0,%1,%2,%3}, {%4,%5,%6,%7}, {%8,%9}, {%0,%1,%2,%3};"
        : "+f"(c0), "+f"(c1), "+f"(c2), "+f"(c3)
        : "r"(a0), "r"(a1), "r"(a2), "r"(a3), "r"(b0), "r"(b1));
}

// One CTA processes 2 batch elements.
//   message[64x128] = nb[64x128] @ w[128x128]   (tf32 tensor cores; scores only)
//   score[n] = sum_e lrelu(self*msg)*q
//   alpha    = softmax per batch (32 neighbors)
//   out[e]   = (sum_n alpha*nb) @ w             (exact fp32 epilogue)
extern "C" __global__ void __launch_bounds__(256, 2)
gat_tc(const float* __restrict__ self_v,
       const float* __restrict__ nbv,
       const float* __restrict__ w,
       const float* __restrict__ q,
       float* __restrict__ out)
{
    extern __shared__ float sm[];
    float* w_s     = sm;                        // 128*132 = 16896
    float* nb_s    = w_s + DD * STR;            // 64*132  =  8448
    float* self_s  = nb_s + ROWS * STR;         // 256 (2 batches)
    float* q_s     = self_s + BPC * DD;         // 128
    float* scoreP  = q_s + DD;                  // 2*64 partials (per e-half)
    float* alpha_s = scoreP + 2 * ROWS;         // 64
    float* agg_s   = alpha_s + ROWS;            // 256

    const int b0 = blockIdx.x * BPC;
    const int t  = threadIdx.x;

    // ---- cooperative loads (padded stores; 132 % 4 == 0 keeps float4 alignment) ----
    {
        const float4* wg = reinterpret_cast<const float4*>(w);
        float4*       ws = reinterpret_cast<float4*>(w_s);
        #pragma unroll
        for (int i = 0; i < 16; ++i) {                  // 4096 float4
            int fi = t + i * 256;
            int d  = fi >> 5, e4 = fi & 31;
            ws[d * (STR / 4) + e4] = wg[fi];
        }
        const float4* ng = reinterpret_cast<const float4*>(nbv + (size_t)b0 * NNB * DD);
        float4*       ns = reinterpret_cast<float4*>(nb_s);
        #pragma unroll
        for (int i = 0; i < 8; ++i) {                   // 2048 float4
            int fi = t + i * 256;
            int rr = fi >> 5, c4 = fi & 31;
            ns[rr * (STR / 4) + c4] = ng[fi];
        }
        self_s[t] = self_v[(size_t)b0 * DD + t];        // 256 = 2 batches
        if (t < DD) q_s[t] = q[t];
    }
    __syncthreads();

    // ---- tf32 MMA: 64x128 output, 8 warps, each warp = 16 rows x 64 cols ----
    const int ww   = t >> 5;
    const int lane = t & 31;
    const int qr   = lane >> 2;       // group id (0..7)
    const int qc   = lane & 3;        // thread in group
    const int m_base = (ww >> 1) * 16;
    const int e_base = (ww & 1) * 64;

    float acc[8][4];
    #pragma unroll
    for (int j = 0; j < 8; ++j)
        #pragma unroll
        for (int k = 0; k < 4; ++k) acc[j][k] = 0.f;

    const float* arow = nb_s + (m_base + qr) * STR + qc;

    #pragma unroll
    for (int k0 = 0; k0 < DD; k0 += 8) {
        const uint32_t a0 = f2tf32(arow[k0]);
        const uint32_t a1 = f2tf32(arow[k0 + 8 * STR]);
        const uint32_t a2 = f2tf32(arow[k0 + 4]);
        const uint32_t a3 = f2tf32(arow[k0 + 8 * STR + 4]);
        const float* bp0 = w_s + (k0 + qc) * STR + e_base + qr;
        #pragma unroll
        for (int j = 0; j < 8; ++j) {
            const uint32_t bb0 = f2tf32(bp0[j * 8]);
            const uint32_t bb1 = f2tf32(bp0[j * 8 + 4 * STR]);
            mma_tf32(acc[j][0], acc[j][1], acc[j][2], acc[j][3],
                     a0, a1, a2, a3, bb0, bb1);
        }
    }

    // ---- scores: p[row] += lrelu(self[e]*msg)*q[e] over this warp's 64 cols ----
    {
        const float* selfb = self_s + (m_base >> 5) * DD;   // whole warp, one batch
        float p_lo = 0.f, p_hi = 0.f;                       // rows m_base+qr, +8
        #pragma unroll
        for (int j = 0; j < 8; ++j) {
            const int e0 = e_base + j * 8 + 2 * qc;
            #pragma unroll
            for (int u = 0; u < 2; ++u) {
                const int e  = e0 + u;
                const float se = selfb[e];
                const float qe = q_s[e];
                float v0 = se * acc[j][u];                  // c0/c1: row lo
                v0 = (v0 >= 0.f) ? v0 : LRELU_ALPHA * v0;
                p_lo = fmaf(v0, qe, p_lo);
                float v1 = se * acc[j][2 + u];              // c2/c3: row hi
                v1 = (v1 >= 0.f) ? v1 : LRELU_ALPHA * v1;
                p_hi = fmaf(v1, qe, p_hi);
            }
        }
        p_lo += __shfl_xor_sync(0xffffffffu, p_lo, 1);
        p_lo += __shfl_xor_sync(0xffffffffu, p_lo, 2);
        p_hi += __shfl_xor_sync(0xffffffffu, p_hi, 1);
        p_hi += __shfl_xor_sync(0xffffffffu, p_hi, 2);
        if (qc == 0) {
            scoreP[(ww & 1) * ROWS + m_base + qr]     = p_lo;
            scoreP[(ww & 1) * ROWS + m_base + qr + 8] = p_hi;
        }
    }
    __syncthreads();

    // ---- softmax per batch: warp0 -> rows 0..31, warp1 -> rows 32..63 ----
    if (t < ROWS) {
        const float s = scoreP[t] + scoreP[ROWS + t];
        float mx = s;
        #pragma unroll
        for (int off = 16; off > 0; off >>= 1)
            mx = fmaxf(mx, __shfl_xor_sync(0xffffffffu, mx, off));
        const float ex = __expf(s - mx);
        float sum = ex;
        #pragma unroll
        for (int off = 16; off > 0; off >>= 1)
            sum += __shfl_xor_sync(0xffffffffu, sum, off);
        alpha_s[t] = ex / sum;
    }
    __syncthreads();

    // ---- agg[bi][d] = sum_n alpha * nb  (exact fp32) ----
    {
        const int bi = t >> 7, d = t & (DD - 1);
        const float* al = alpha_s + bi * NNB;
        const float* nr = nb_s + bi * NNB * STR + d;
        float a = 0.f;
        #pragma unroll
        for (int n = 0; n < NNB; ++n)
            a = fmaf(al[n], nr[n * STR], a);
        agg_s[bi * DD + d] = a;
    }
    __syncthreads();

    // ---- out[bi][e] = sum_d agg * w  (exact fp32) ----
    {
        const int bi = t >> 7, e = t & (DD - 1);
        const float* ag = agg_s + bi * DD;
        float o0 = 0.f, o1 = 0.f;
        #pragma unroll 8
        for (int d = 0; d < DD; d += 2) {
            o0 = fmaf(ag[d],     w_s[d * STR + e],        o0);
            o1 = fmaf(ag[d + 1], w_s[(d + 1) * STR + e],  o1);
        }
        out[(size_t)(b0 + bi) * DD + e] = o0 + o1;
    }
}

extern "C" void kernel_launch(void* const* d_in, const int* in_sizes, int n_in,
                              void* d_out, int out_size)
{
    const float* self_v = (const float*)d_in[0];   // [B,128]
    const float* nbv    = (const float*)d_in[1];   // [B,32,128]
    const float* w      = (const float*)d_in[2];   // [128,128]
    const float* q      = (const float*)d_in[3];   // [128,1]
    float*       out    = (float*)d_out;           // [B,128]

    const int B = in_sizes[0] / DD;                // 20000

    const size_t smem_bytes =
        (size_t)(DD * STR + ROWS * STR + BPC * DD + DD + 2 * ROWS + ROWS + BPC * DD)
        * sizeof(float);                           // 104704 B

    cudaFuncSetAttribute(gat_tc, cudaFuncAttributeMaxDynamicSharedMemorySize,
                         (int)smem_bytes);

    gat_tc<<<B / BPC, 256, smem_bytes>>>(self_v, nbv, w, q, out);
}

// round 3
// speedup vs baseline: 2.3533x; 1.0696x over previous
#include <cuda_runtime.h>
#include <cstdint>

#define DD    128
#define NNB   32
#define BPC   2
#define ROWS  (BPC * NNB)      // 64
#define STRW  132              // w_s row stride (floats), fragment-major layout
#define STRA  144              // nb_s row stride (floats)
#define LRELU_ALPHA 0.2f

// w_s  : pos(d,e) = d*STRW + (e&7)*16 + (e>>3)
// nb_s : pos(r,d) = r*STRA + (d&3)*36 + (d>>2)

__device__ __forceinline__ void mma_tf32(float& c0, float& c1, float& c2, float& c3,
                                         float a0, float a1, float a2, float a3,
                                         float b0, float b1) {
    // raw fp32 bits: HMMA.TF32 uses bits[31:13] (truncation) — no cvt needed
    asm volatile(
        "mma.sync.aligned.m16n8k8.row.col.f32.tf32.tf32.f32 "
        "{%0,%1,%2,%3}, {%4,%5,%6,%7}, {%8,%9}, {%0,%1,%2,%3};"
        : "+f"(c0), "+f"(c1), "+f"(c2), "+f"(c3)
        : "r"(__float_as_uint(a0)), "r"(__float_as_uint(a1)),
          "r"(__float_as_uint(a2)), "r"(__float_as_uint(a3)),
          "r"(__float_as_uint(b0)), "r"(__float_as_uint(b1)));
}

extern "C" __global__ void __launch_bounds__(256, 2)
gat_tc3(const float* __restrict__ self_v,
        const float* __restrict__ nbv,
        const float* __restrict__ w,
        const float* __restrict__ q,
        float* __restrict__ out)
{
    extern __shared__ float sm[];
    float* w_s     = sm;                        // 128*132 = 16896
    float* nb_s    = w_s + DD * STRW;           // 64*144  =  9216
    float* self_s  = nb_s + ROWS * STRA;        // 256
    float* q_s     = self_s + BPC * DD;         // 128
    float* scoreP  = q_s + DD;                  // 2*64
    float* alpha_s = scoreP + 2 * ROWS;         // 64
    float* agg_s   = alpha_s + ROWS;            // 256

    const int b0 = blockIdx.x * BPC;
    const int t  = threadIdx.x;

    // ---- gmem -> smem (scatter into fragment-major layouts) ----
    {
        const float4* wg = reinterpret_cast<const float4*>(w);
        #pragma unroll
        for (int i = 0; i < 16; ++i) {            // 4096 float4
            const int fi = t + i * 256;
            const int d  = fi >> 5, e4 = fi & 31;
            const float4 v = wg[fi];
            const int e0 = 4 * e4;
            w_s[d * STRW + ((e0 + 0) & 7) * 16 + ((e0 + 0) >> 3)] = v.x;
            w_s[d * STRW + ((e0 + 1) & 7) * 16 + ((e0 + 1) >> 3)] = v.y;
            w_s[d * STRW + ((e0 + 2) & 7) * 16 + ((e0 + 2) >> 3)] = v.z;
            w_s[d * STRW + ((e0 + 3) & 7) * 16 + ((e0 + 3) >> 3)] = v.w;
        }
        const float4* ng = reinterpret_cast<const float4*>(nbv + (size_t)b0 * NNB * DD);
        #pragma unroll
        for (int i = 0; i < 8; ++i) {             // 2048 float4
            const int fi = t + i * 256;
            const int r  = fi >> 5, d4 = fi & 31;
            const float4 v = ng[fi];
            float* base = nb_s + r * STRA + d4;
            base[0 * 36] = v.x;
            base[1 * 36] = v.y;
            base[2 * 36] = v.z;
            base[3 * 36] = v.w;
        }
        self_s[t] = self_v[(size_t)b0 * DD + t];
        if (t < DD) q_s[t] = q[t];
    }
    __syncthreads();

    // ---- tf32 MMA mainloop: warp = 16 rows x 64 cols ----
    const int ww     = t >> 5;
    const int lane   = t & 31;
    const int qr     = lane >> 2;
    const int qc     = lane & 3;
    const int m_base = (ww >> 1) * 16;
    const int e_half = ww & 1;

    float acc[8][4];
    #pragma unroll
    for (int j = 0; j < 8; ++j)
        #pragma unroll
        for (int k = 0; k < 4; ++k) acc[j][k] = 0.f;

    const float* aptr0 = nb_s + (m_base + qr) * STRA + qc * 36;   // rows qr
    const float* aptr1 = aptr0 + 8 * STRA;                        // rows qr+8
    const float* bptr  = w_s + qc * STRW + qr * 16 + e_half * 8;  // k-row qc

    #pragma unroll
    for (int k0 = 0; k0 < DD; k0 += 16) {
        const float4 A0 = *reinterpret_cast<const float4*>(aptr0 + (k0 >> 2));
        const float4 A1 = *reinterpret_cast<const float4*>(aptr1 + (k0 >> 2));
        #pragma unroll
        for (int s = 0; s < 2; ++s) {
            const float* bk = bptr + (k0 + 8 * s) * STRW;
            const float4 B0  = *reinterpret_cast<const float4*>(bk);            // row k, j 0..3
            const float4 B0b = *reinterpret_cast<const float4*>(bk + 4);        // row k, j 4..7
            const float4 B1  = *reinterpret_cast<const float4*>(bk + 4 * STRW); // row k+4
            const float4 B1b = *reinterpret_cast<const float4*>(bk + 4 * STRW + 4);
            const float a0 = s ? A0.z : A0.x;   // (row qr,   k+qc)
            const float a2 = s ? A0.w : A0.y;   // (row qr,   k+qc+4)
            const float a1 = s ? A1.z : A1.x;   // (row qr+8, k+qc)
            const float a3 = s ? A1.w : A1.y;   // (row qr+8, k+qc+4)
            mma_tf32(acc[0][0], acc[0][1], acc[0][2], acc[0][3], a0,a1,a2,a3, B0.x,  B1.x);
            mma_tf32(acc[1][0], acc[1][1], acc[1][2], acc[1][3], a0,a1,a2,a3, B0.y,  B1.y);
            mma_tf32(acc[2][0], acc[2][1], acc[2][2], acc[2][3], a0,a1,a2,a3, B0.z,  B1.z);
            mma_tf32(acc[3][0], acc[3][1], acc[3][2], acc[3][3], a0,a1,a2,a3, B0.w,  B1.w);
            mma_tf32(acc[4][0], acc[4][1], acc[4][2], acc[4][3], a0,a1,a2,a3, B0b.x, B1b.x);
            mma_tf32(acc[5][0], acc[5][1], acc[5][2], acc[5][3], a0,a1,a2,a3, B0b.y, B1b.y);
            mma_tf32(acc[6][0], acc[6][1], acc[6][2], acc[6][3], a0,a1,a2,a3, B0b.z, B1b.z);
            mma_tf32(acc[7][0], acc[7][1], acc[7][2], acc[7][3], a0,a1,a2,a3, B0b.w, B1b.w);
        }
    }

    // ---- scores: lrelu(self[e]*msg)*q[e], reduce over this warp's 64 cols ----
    {
        const float* selfb = self_s + (m_base >> 5) * DD;  // batch of this m-block
        float p_lo = 0.f, p_hi = 0.f;                      // rows m_base+qr, +8
        #pragma unroll
        for (int j = 0; j < 8; ++j) {
            const int e0 = e_half * 64 + j * 8 + 2 * qc;
            #pragma unroll
            for (int u = 0; u < 2; ++u) {
                const int e  = e0 + u;
                const float se = selfb[e];
                const float qe = q_s[e];
                float v0 = se * acc[j][u];
                v0 = (v0 >= 0.f) ? v0 : LRELU_ALPHA * v0;
                p_lo = fmaf(v0, qe, p_lo);
                float v1 = se * acc[j][2 + u];
                v1 = (v1 >= 0.f) ? v1 : LRELU_ALPHA * v1;
                p_hi = fmaf(v1, qe, p_hi);
            }
        }
        p_lo += __shfl_xor_sync(0xffffffffu, p_lo, 1);
        p_lo += __shfl_xor_sync(0xffffffffu, p_lo, 2);
        p_hi += __shfl_xor_sync(0xffffffffu, p_hi, 1);
        p_hi += __shfl_xor_sync(0xffffffffu, p_hi, 2);
        if (qc == 0) {
            scoreP[e_half * ROWS + m_base + qr]     = p_lo;
            scoreP[e_half * ROWS + m_base + qr + 8] = p_hi;
        }
    }
    __syncthreads();

    // ---- softmax per batch (rows = 32 neighbors) ----
    if (t < ROWS) {
        const float s = scoreP[t] + scoreP[ROWS + t];
        float mx = s;
        #pragma unroll
        for (int off = 16; off > 0; off >>= 1)
            mx = fmaxf(mx, __shfl_xor_sync(0xffffffffu, mx, off));
        const float ex = __expf(s - mx);
        float sum = ex;
        #pragma unroll
        for (int off = 16; off > 0; off >>= 1)
            sum += __shfl_xor_sync(0xffffffffu, sum, off);
        alpha_s[t] = ex / sum;
    }
    __syncthreads();

    // ---- agg[bi][d] = sum_n alpha*nb (exact fp32; bank-permuted lane->d) ----
    {
        const int bi = ww >> 2;            // batch
        const int w4 = ww & 3;
        const int a  = lane & 3;
        const int g  = ((lane >> 2) + 4 * a + 8 * w4) & 31;
        const int d  = 4 * g + a;
        const float* np = nb_s + bi * NNB * STRA + a * 36 + g;
        const float* al = alpha_s + bi * NNB;
        float acc_a = 0.f;
        #pragma unroll
        for (int n = 0; n < NNB; ++n)
            acc_a = fmaf(al[n], np[n * STRA], acc_a);
        agg_s[bi * DD + d] = acc_a;
    }
    __syncthreads();

    // ---- out[bi][e] = sum_d agg*w (exact fp32; bank-permuted lane->e) ----
    {
        const int bi = ww >> 2;
        const int c  = ww & 3;
        const int e  = 8 * (lane >> 1) + 2 * c + (lane & 1);
        const float* wp = w_s + (2 * c + (lane & 1)) * 16 + (lane >> 1);
        const float* ag = agg_s + bi * DD;
        float o0 = 0.f, o1 = 0.f;
        #pragma unroll 8
        for (int d = 0; d < DD; d += 2) {
            o0 = fmaf(ag[d],     wp[d * STRW],       o0);
            o1 = fmaf(ag[d + 1], wp[(d + 1) * STRW], o1);
        }
        out[(size_t)(b0 + bi) * DD + e] = o0 + o1;
    }
}

extern "C" void kernel_launch(void* const* d_in, const int* in_sizes, int n_in,
                              void* d_out, int out_size)
{
    const float* self_v = (const float*)d_in[0];   // [B,128]
    const float* nbv    = (const float*)d_in[1];   // [B,32,128]
    const float* w      = (const float*)d_in[2];   // [128,128]
    const float* q      = (const float*)d_in[3];   // [128,1]
    float*       out    = (float*)d_out;           // [B,128]

    const int B = in_sizes[0] / DD;                // 20000

    const size_t smem_bytes =
        (size_t)(DD * STRW + ROWS * STRA + BPC * DD + DD + 2 * ROWS + ROWS + BPC * DD)
        * sizeof(float);                           // 107776 B

    cudaFuncSetAttribute(gat_tc3, cudaFuncAttributeMaxDynamicSharedMemorySize,
                         (int)smem_bytes);

    gat_tc3<<<B / BPC, 256, smem_bytes>>>(self_v, nbv, w, q, out);
}

// round 4
// speedup vs baseline: 2.9380x; 1.2485x over previous
#include <cuda_runtime.h>
#include <cstdint>

#define DD    128
#define NNB   32
#define STRW  132              // w_s stride (fragment-major layout)
#define STRA  132              // nb_s stride (row-major, padded)
#define LRELU_ALPHA 0.2f

// w_s : pos(d,e) = d*STRW + (e&7)*16 + (e>>3)   (B-frags + gemv both conflict-free)

__device__ __forceinline__ uint32_t cvt_tf32(float f) {
    uint32_t r;
    asm("cvt.rna.tf32.f32 %0, %1;" : "=r"(r) : "f"(f));
    return r;
}

__device__ __forceinline__ void mma_tf32(float& c0, float& c1, float& c2, float& c3,
                                         uint32_t a0, uint32_t a1, uint32_t a2, uint32_t a3,
                                         float b0, float b1) {
    asm volatile(
        "mma.sync.aligned.m16n8k8.row.col.f32.tf32.tf32.f32 "
        "{%0,%1,%2,%3}, {%4,%5,%6,%7}, {%8,%9}, {%0,%1,%2,%3};"
        : "+f"(c0), "+f"(c1), "+f"(c2), "+f"(c3)
        : "r"(a0), "r"(a1), "r"(a2), "r"(a3),
          "r"(__float_as_uint(b0)), "r"(__float_as_uint(b1)));
}

__device__ __forceinline__ void cp_async16(uint32_t smem_addr, const void* gptr) {
    asm volatile("cp.async.cg.shared.global [%0], [%1], 16;\n"
                 :: "r"(smem_addr), "l"(gptr));
}
__device__ __forceinline__ void cp_commit() {
    asm volatile("cp.async.commit_group;\n" ::);
}
__device__ __forceinline__ void cp_wait1() {
    asm volatile("cp.async.wait_group 1;\n" ::);
}

// Persistent kernel: each CTA loads w ONCE into fragment-major smem, then loops
// over its share of batches with double-buffered cp.async nb tiles.
extern "C" __global__ void __launch_bounds__(256, 2)
gat_persist(const float* __restrict__ self_v,
            const float* __restrict__ nbv,
            const float* __restrict__ w,
            const float* __restrict__ q,
            float* __restrict__ out,
            int B)
{
    extern __shared__ float sm[];
    float* w_s     = sm;                         // 128*132 = 16896
    float* nb_s    = w_s + DD * STRW;            // 2 * 32*132 = 8448
    float* self_s  = nb_s + 2 * NNB * STRA;      // 2*128
    float* q_s     = self_s + 2 * DD;            // 128
    float* scoreP  = q_s + DD;                   // 4*32
    float* alpha_s = scoreP + 4 * NNB;           // 32
    float* agg_s   = alpha_s + NNB;              // 128

    const int t    = threadIdx.x;
    const int lane = t & 31;
    const int ww   = t >> 5;
    const int qr   = lane >> 2;
    const int qc   = lane & 3;
    const int mb   = ww >> 2;                    // m_base = 16*mb
    const int eb   = ww & 3;                     // e_base = 32*eb

    // ---- one-time init: w -> fragment-major smem, q ----
    {
        const float4* wg = reinterpret_cast<const float4*>(w);
        #pragma unroll
        for (int i = 0; i < 16; ++i) {
            const int fi = t + i * 256;
            const int d  = fi >> 5, e4 = fi & 31;
            const float4 v = wg[fi];
            const int e0 = 4 * e4;
            w_s[d * STRW + ((e0 + 0) & 7) * 16 + ((e0 + 0) >> 3)] = v.x;
            w_s[d * STRW + ((e0 + 1) & 7) * 16 + ((e0 + 1) >> 3)] = v.y;
            w_s[d * STRW + ((e0 + 2) & 7) * 16 + ((e0 + 2) >> 3)] = v.z;
            w_s[d * STRW + ((e0 + 3) & 7) * 16 + ((e0 + 3) >> 3)] = v.w;
        }
        if (t < DD) q_s[t] = q[t];
    }

    // ---- tile prefetch helper ----
    auto issue_tile = [&](int p, int buf) {
        if (p < B) {
            const float4* src = reinterpret_cast<const float4*>(nbv + (size_t)p * NNB * DD);
            const uint32_t dst0 =
                (uint32_t)__cvta_generic_to_shared(nb_s + buf * NNB * STRA);
            #pragma unroll
            for (int i = 0; i < 4; ++i) {                 // 1024 float4 / 256 thr
                const int fi = t + i * 256;
                const int r  = fi >> 5, c4 = fi & 31;
                cp_async16(dst0 + (uint32_t)(r * STRA + 4 * c4) * 4u, src + fi);
            }
            if (t < 32) {
                const uint32_t ds =
                    (uint32_t)__cvta_generic_to_shared(self_s + buf * DD) + t * 16u;
                cp_async16(ds, reinterpret_cast<const float4*>(self_v + (size_t)p * DD) + t);
            }
        }
        cp_commit();
    };

    // prologue: two tiles in flight
    issue_tile(blockIdx.x, 0);
    issue_tile(blockIdx.x + gridDim.x, 1);

    int it = 0;
    for (int p = blockIdx.x; p < B; p += gridDim.x, ++it) {
        const int cur = it & 1;
        cp_wait1();
        __syncthreads();                         // tile[cur] (+ w_s on iter 0) visible

        const float* nbuf = nb_s + cur * NNB * STRA;

        // ---- tf32 MMA: warp tile = 16 rows x 32 cols ----
        float acc[4][4];
        #pragma unroll
        for (int j = 0; j < 4; ++j)
            #pragma unroll
            for (int k = 0; k < 4; ++k) acc[j][k] = 0.f;

        const float* ar0 = nbuf + (16 * mb + qr) * STRA + qc;
        const float* ar1 = ar0 + 8 * STRA;
        const float* bp  = w_s + qc * STRW + qr * 16 + 4 * eb;

        #pragma unroll 8
        for (int k0 = 0; k0 < DD; k0 += 8) {
            const uint32_t a0 = cvt_tf32(ar0[k0]);
            const uint32_t a2 = cvt_tf32(ar0[k0 + 4]);
            const uint32_t a1 = cvt_tf32(ar1[k0]);
            const uint32_t a3 = cvt_tf32(ar1[k0 + 4]);
            const float* bk = bp + k0 * STRW;
            const float4 B0 = *reinterpret_cast<const float4*>(bk);            // b0, j=0..3
            const float4 B1 = *reinterpret_cast<const float4*>(bk + 4 * STRW); // b1, j=0..3
            mma_tf32(acc[0][0], acc[0][1], acc[0][2], acc[0][3], a0,a1,a2,a3, B0.x, B1.x);
            mma_tf32(acc[1][0], acc[1][1], acc[1][2], acc[1][3], a0,a1,a2,a3, B0.y, B1.y);
            mma_tf32(acc[2][0], acc[2][1], acc[2][2], acc[2][3], a0,a1,a2,a3, B0.z, B1.z);
            mma_tf32(acc[3][0], acc[3][1], acc[3][2], acc[3][3], a0,a1,a2,a3, B0.w, B1.w);
        }

        // ---- score partials: lrelu(self[e]*msg)*q[e], reduce over 32 cols ----
        {
            const float* selfb = self_s + cur * DD;
            float p_lo = 0.f, p_hi = 0.f;            // rows 16mb+qr, +8
            #pragma unroll
            for (int j = 0; j < 4; ++j) {
                const int e0 = 32 * eb + 8 * j + 2 * qc;
                #pragma unroll
                for (int u = 0; u < 2; ++u) {
                    const int e  = e0 + u;
                    const float se = selfb[e];
                    const float qe = q_s[e];
                    float v0 = se * acc[j][u];
                    v0 = (v0 >= 0.f) ? v0 : LRELU_ALPHA * v0;
                    p_lo = fmaf(v0, qe, p_lo);
                    float v1 = se * acc[j][2 + u];
                    v1 = (v1 >= 0.f) ? v1 : LRELU_ALPHA * v1;
                    p_hi = fmaf(v1, qe, p_hi);
                }
            }
            p_lo += __shfl_xor_sync(0xffffffffu, p_lo, 1);
            p_lo += __shfl_xor_sync(0xffffffffu, p_lo, 2);
            p_hi += __shfl_xor_sync(0xffffffffu, p_hi, 1);
            p_hi += __shfl_xor_sync(0xffffffffu, p_hi, 2);
            if (qc == 0) {
                scoreP[eb * NNB + 16 * mb + qr]     = p_lo;
                scoreP[eb * NNB + 16 * mb + qr + 8] = p_hi;
            }
        }
        __syncthreads();

        // ---- softmax over 32 neighbors (warp 0) ----
        if (t < NNB) {
            const float s = scoreP[t] + scoreP[NNB + t]
                          + scoreP[2 * NNB + t] + scoreP[3 * NNB + t];
            float mx = s;
            #pragma unroll
            for (int off = 16; off > 0; off >>= 1)
                mx = fmaxf(mx, __shfl_xor_sync(0xffffffffu, mx, off));
            const float ex = __expf(s - mx);
            float sum = ex;
            #pragma unroll
            for (int off = 16; off > 0; off >>= 1)
                sum += __shfl_xor_sync(0xffffffffu, sum, off);
            alpha_s[t] = ex / sum;
        }
        __syncthreads();

        // ---- agg[d] = sum_n alpha*nb (exact fp32) ----
        if (t < DD) {
            float a = 0.f;
            const float* np = nbuf + t;
            #pragma unroll
            for (int n = 0; n < NNB; ++n)
                a = fmaf(alpha_s[n], np[n * STRA], a);
            agg_s[t] = a;
        }
        __syncthreads();                         // nb[cur]/self[cur] now dead

        // prefetch two batches ahead into the freed buffer
        issue_tile(p + 2 * gridDim.x, cur);

        // ---- out[e] = sum_d agg*w (exact fp32; bank-permuted lane->e) ----
        if (t < DD) {
            const int c  = ww & 3;
            const int e  = 8 * (lane >> 1) + 2 * c + (lane & 1);
            const float* wp = w_s + (e & 7) * 16 + (e >> 3);
            float o0 = 0.f, o1 = 0.f;
            #pragma unroll 8
            for (int d = 0; d < DD; d += 2) {
                o0 = fmaf(agg_s[d],     wp[d * STRW],       o0);
                o1 = fmaf(agg_s[d + 1], wp[(d + 1) * STRW], o1);
            }
            out[(size_t)p * DD + e] = o0 + o1;
        }
        // loop-top __syncthreads orders gemv reads vs next iter's smem writes
    }
}

extern "C" void kernel_launch(void* const* d_in, const int* in_sizes, int n_in,
                              void* d_out, int out_size)
{
    const float* self_v = (const float*)d_in[0];   // [B,128]
    const float* nbv    = (const float*)d_in[1];   // [B,32,128]
    const float* w      = (const float*)d_in[2];   // [128,128]
    const float* q      = (const float*)d_in[3];   // [128,1]
    float*       out    = (float*)d_out;           // [B,128]

    const int B = in_sizes[0] / DD;                // 20000

    int smc = 0;
    cudaDeviceGetAttribute(&smc, cudaDevAttrMultiProcessorCount, 0);
    if (smc <= 0) smc = 148;
    int grid = 2 * smc;
    if (grid > B) grid = B;

    const size_t smem_bytes =
        (size_t)(DD * STRW + 2 * NNB * STRA + 2 * DD + DD + 4 * NNB + NNB + DD)
        * sizeof(float);                           // 104064 B

    cudaFuncSetAttribute(gat_persist, cudaFuncAttributeMaxDynamicSharedMemorySize,
                         (int)smem_bytes);

    gat_persist<<<grid, 256, smem_bytes>>>(self_v, nbv, w, q, out, B);
}

// round 5
// speedup vs baseline: 4.1201x; 1.4023x over previous
#include <cuda_runtime.h>
#include <cstdint>

#define DD    128
#define NNB   32
#define STRW  132
#define STRA  132
#define LRELU_ALPHA 0.2f

// w_s : pos(d,e) = d*STRW + (e&7)*16 + (e>>3), values pre-rounded to tf32 (rna)

__device__ __forceinline__ uint32_t cvt_tf32(float f) {
    uint32_t r;
    asm("cvt.rna.tf32.f32 %0, %1;" : "=r"(r) : "f"(f));
    return r;
}
__device__ __forceinline__ float cvt_tf32f(float f) {
    return __uint_as_float(cvt_tf32(f));
}

__device__ __forceinline__ void mma_tf32(float& c0, float& c1, float& c2, float& c3,
                                         uint32_t a0, uint32_t a1, uint32_t a2, uint32_t a3,
                                         float b0, float b1) {
    asm volatile(
        "mma.sync.aligned.m16n8k8.row.col.f32.tf32.tf32.f32 "
        "{%0,%1,%2,%3}, {%4,%5,%6,%7}, {%8,%9}, {%0,%1,%2,%3};"
        : "+f"(c0), "+f"(c1), "+f"(c2), "+f"(c3)
        : "r"(a0), "r"(a1), "r"(a2), "r"(a3),
          "r"(__float_as_uint(b0)), "r"(__float_as_uint(b1)));
}

__device__ __forceinline__ void cp_async16(uint32_t smem_addr, const void* gptr) {
    asm volatile("cp.async.cg.shared.global [%0], [%1], 16;\n"
                 :: "r"(smem_addr), "l"(gptr));
}
__device__ __forceinline__ void cp_commit() {
    asm volatile("cp.async.commit_group;\n" ::);
}
__device__ __forceinline__ void cp_wait1() {
    asm volatile("cp.async.wait_group 1;\n" ::);
}

// Persistent CTA, w resident in smem (tf32-rounded once). 4 MMA warps, each
// 32 rows x 32 cols. Output produced straight from accumulators:
//   out[e] = sum_n alpha[n] * msg[n][e]   (msg lives in registers).
extern "C" __global__ void __launch_bounds__(256, 2)
gat_reg(const float* __restrict__ self_v,
        const float* __restrict__ nbv,
        const float* __restrict__ w,
        const float* __restrict__ q,
        float* __restrict__ out,
        int B)
{
    extern __shared__ float sm[];
    float* w_s     = sm;                         // 128*132 = 16896
    float* nb_s    = w_s + DD * STRW;            // 2 * 32*132 = 8448
    float* self_s  = nb_s + 2 * NNB * STRA;      // 2*128
    float* q_s     = self_s + 2 * DD;            // 128
    float* scoreP  = q_s + DD;                   // 4*32
    float* alpha_s = scoreP + 4 * NNB;           // 32

    const int t    = threadIdx.x;
    const int lane = t & 31;
    const int ww   = t >> 5;
    const int qr   = lane >> 2;      // 0..7
    const int qc   = lane & 3;       // 0..3
    const bool is_mma = (ww < 4);
    const int eb   = ww & 3;         // col block for mma warps

    // ---- one-time: w -> fragment-major smem, pre-rounded to tf32 ----
    {
        const float4* wg = reinterpret_cast<const float4*>(w);
        #pragma unroll
        for (int i = 0; i < 16; ++i) {
            const int fi = t + i * 256;
            const int d  = fi >> 5, e4 = fi & 31;
            const float4 v = wg[fi];
            const int e0 = 4 * e4;
            w_s[d * STRW + ((e0 + 0) & 7) * 16 + ((e0 + 0) >> 3)] = cvt_tf32f(v.x);
            w_s[d * STRW + ((e0 + 1) & 7) * 16 + ((e0 + 1) >> 3)] = cvt_tf32f(v.y);
            w_s[d * STRW + ((e0 + 2) & 7) * 16 + ((e0 + 2) >> 3)] = cvt_tf32f(v.z);
            w_s[d * STRW + ((e0 + 3) & 7) * 16 + ((e0 + 3) >> 3)] = cvt_tf32f(v.w);
        }
        if (t < DD) q_s[t] = q[t];
    }

    auto issue_tile = [&](int p, int buf) {
        if (p < B) {
            const float4* src = reinterpret_cast<const float4*>(nbv + (size_t)p * NNB * DD);
            const uint32_t dst0 =
                (uint32_t)__cvta_generic_to_shared(nb_s + buf * NNB * STRA);
            #pragma unroll
            for (int i = 0; i < 4; ++i) {                 // 1024 float4 / 256 thr
                const int fi = t + i * 256;
                const int r  = fi >> 5, c4 = fi & 31;
                cp_async16(dst0 + (uint32_t)(r * STRA + 4 * c4) * 4u, src + fi);
            }
            if (t < 32) {
                const uint32_t ds =
                    (uint32_t)__cvta_generic_to_shared(self_s + buf * DD) + t * 16u;
                cp_async16(ds, reinterpret_cast<const float4*>(self_v + (size_t)p * DD) + t);
            }
        }
        cp_commit();
    };

    issue_tile(blockIdx.x, 0);
    issue_tile(blockIdx.x + gridDim.x, 1);

    int it = 0;
    for (int p = blockIdx.x; p < B; p += gridDim.x, ++it) {
        const int cur = it & 1;
        cp_wait1();
        __syncthreads();                          // tile[cur] (+ w_s on iter 0) visible

        const float* nbuf = nb_s + cur * NNB * STRA;

        float acc[2][4][4];                       // [m-tile T][n-tile j][frag]
        if (is_mma) {
            #pragma unroll
            for (int T = 0; T < 2; ++T)
                #pragma unroll
                for (int j = 0; j < 4; ++j)
                    #pragma unroll
                    for (int k = 0; k < 4; ++k) acc[T][j][k] = 0.f;

            const float* a00 = nbuf + qr * STRA + qc;            // T0 rows qr / qr+8
            const float* a10 = a00 + 16 * STRA;                  // T1 rows 16+qr / 24+qr
            const float* bp  = w_s + qc * STRW + qr * 16 + 4 * eb;

            #pragma unroll
            for (int k0 = 0; k0 < DD; k0 += 8) {
                const uint32_t a0 = cvt_tf32(a00[k0]);
                const uint32_t a1 = cvt_tf32(a00[k0 + 8 * STRA]);
                const uint32_t a2 = cvt_tf32(a00[k0 + 4]);
                const uint32_t a3 = cvt_tf32(a00[k0 + 8 * STRA + 4]);
                const uint32_t c0 = cvt_tf32(a10[k0]);
                const uint32_t c1 = cvt_tf32(a10[k0 + 8 * STRA]);
                const uint32_t c2 = cvt_tf32(a10[k0 + 4]);
                const uint32_t c3 = cvt_tf32(a10[k0 + 8 * STRA + 4]);
                const float* bk = bp + k0 * STRW;
                const float4 B0 = *reinterpret_cast<const float4*>(bk);            // k=qc
                const float4 B1 = *reinterpret_cast<const float4*>(bk + 4 * STRW); // k=qc+4
                mma_tf32(acc[0][0][0],acc[0][0][1],acc[0][0][2],acc[0][0][3], a0,a1,a2,a3, B0.x,B1.x);
                mma_tf32(acc[1][0][0],acc[1][0][1],acc[1][0][2],acc[1][0][3], c0,c1,c2,c3, B0.x,B1.x);
                mma_tf32(acc[0][1][0],acc[0][1][1],acc[0][1][2],acc[0][1][3], a0,a1,a2,a3, B0.y,B1.y);
                mma_tf32(acc[1][1][0],acc[1][1][1],acc[1][1][2],acc[1][1][3], c0,c1,c2,c3, B0.y,B1.y);
                mma_tf32(acc[0][2][0],acc[0][2][1],acc[0][2][2],acc[0][2][3], a0,a1,a2,a3, B0.z,B1.z);
                mma_tf32(acc[1][2][0],acc[1][2][1],acc[1][2][2],acc[1][2][3], c0,c1,c2,c3, B0.z,B1.z);
                mma_tf32(acc[0][3][0],acc[0][3][1],acc[0][3][2],acc[0][3][3], a0,a1,a2,a3, B0.w,B1.w);
                mma_tf32(acc[1][3][0],acc[1][3][1],acc[1][3][2],acc[1][3][3], c0,c1,c2,c3, B0.w,B1.w);
            }

            // ---- score partials over this warp's 32 cols ----
            const float* selfb = self_s + cur * DD;
            float pr[4] = {0.f, 0.f, 0.f, 0.f};   // rows qr, qr+8, 16+qr, 24+qr
            #pragma unroll
            for (int j = 0; j < 4; ++j) {
                const int e0 = 32 * eb + 8 * j + 2 * qc;
                #pragma unroll
                for (int u = 0; u < 2; ++u) {
                    const int e  = e0 + u;
                    const float sq = selfb[e];
                    const float qe = q_s[e];
                    #pragma unroll
                    for (int T = 0; T < 2; ++T) {
                        float v0 = sq * acc[T][j][u];
                        v0 = (v0 >= 0.f) ? v0 : LRELU_ALPHA * v0;
                        pr[2 * T] = fmaf(v0, qe, pr[2 * T]);
                        float v1 = sq * acc[T][j][2 + u];
                        v1 = (v1 >= 0.f) ? v1 : LRELU_ALPHA * v1;
                        pr[2 * T + 1] = fmaf(v1, qe, pr[2 * T + 1]);
                    }
                }
            }
            #pragma unroll
            for (int i = 0; i < 4; ++i) {
                pr[i] += __shfl_xor_sync(0xffffffffu, pr[i], 1);
                pr[i] += __shfl_xor_sync(0xffffffffu, pr[i], 2);
            }
            if (qc == 0) {
                scoreP[eb * NNB + qr]      = pr[0];
                scoreP[eb * NNB + qr + 8]  = pr[1];
                scoreP[eb * NNB + qr + 16] = pr[2];
                scoreP[eb * NNB + qr + 24] = pr[3];
            }
        }
        __syncthreads();

        // ---- softmax over 32 neighbors (warp 0) ----
        if (t < NNB) {
            const float s = scoreP[t] + scoreP[NNB + t]
                          + scoreP[2 * NNB + t] + scoreP[3 * NNB + t];
            float mx = s;
            #pragma unroll
            for (int off = 16; off > 0; off >>= 1)
                mx = fmaxf(mx, __shfl_xor_sync(0xffffffffu, mx, off));
            const float ex = __expf(s - mx);
            float sum = ex;
            #pragma unroll
            for (int off = 16; off > 0; off >>= 1)
                sum += __shfl_xor_sync(0xffffffffu, sum, off);
            alpha_s[t] = ex / sum;
        }
        __syncthreads();                          // alpha ready; nb[cur] dead after mainloop

        issue_tile(p + 2 * gridDim.x, cur);       // refill freed buffer

        // ---- out[e] = sum_n alpha[n]*acc  (register epilogue) ----
        if (is_mma) {
            const float al0 = alpha_s[qr];        // row qr       (T0 lo)
            const float al1 = alpha_s[qr + 8];    // row qr+8     (T0 hi)
            const float al2 = alpha_s[qr + 16];   // row 16+qr    (T1 lo)
            const float al3 = alpha_s[qr + 24];   // row 24+qr    (T1 hi)
            float val[4][2];
            #pragma unroll
            for (int j = 0; j < 4; ++j)
                #pragma unroll
                for (int u = 0; u < 2; ++u) {
                    float v = al0 * acc[0][j][u];
                    v = fmaf(al1, acc[0][j][2 + u], v);
                    v = fmaf(al2, acc[1][j][u], v);
                    v = fmaf(al3, acc[1][j][2 + u], v);
                    #pragma unroll
                    for (int off = 4; off < 32; off <<= 1)   // reduce over qr lanes
                        v += __shfl_xor_sync(0xffffffffu, v, off);
                    val[j][u] = v;
                }
            if (qr == 0) {
                float* op = out + (size_t)p * DD + 32 * eb + 2 * qc;
                #pragma unroll
                for (int j = 0; j < 4; ++j) {
                    op[8 * j]     = val[j][0];
                    op[8 * j + 1] = val[j][1];
                }
            }
        }
        // loop-top __syncthreads orders next tile's smem writes vs these reads
    }
}

extern "C" void kernel_launch(void* const* d_in, const int* in_sizes, int n_in,
                              void* d_out, int out_size)
{
    const float* self_v = (const float*)d_in[0];   // [B,128]
    const float* nbv    = (const float*)d_in[1];   // [B,32,128]
    const float* w      = (const float*)d_in[2];   // [128,128]
    const float* q      = (const float*)d_in[3];   // [128,1]
    float*       out    = (float*)d_out;           // [B,128]

    const int B = in_sizes[0] / DD;                // 20000

    int smc = 0;
    cudaDeviceGetAttribute(&smc, cudaDevAttrMultiProcessorCount, 0);
    if (smc <= 0) smc = 148;
    int grid = 2 * smc;
    if (grid > B) grid = B;

    const size_t smem_bytes =
        (size_t)(DD * STRW + 2 * NNB * STRA + 2 * DD + DD + 4 * NNB + NNB)
        * sizeof(float);                           // 103,552 B

    cudaFuncSetAttribute(gat_reg, cudaFuncAttributeMaxDynamicSharedMemorySize,
                         (int)smem_bytes);

    gat_reg<<<grid, 256, smem_bytes>>>(self_v, nbv, w, q, out, B);
}